// round 1
// baseline (speedup 1.0000x reference)
#include <cuda_runtime.h>

// SpatialCNN: 4 directional scans, each step: out[p] += relu(conv1d_C2C(out[p_prev]))
// Shapes: x (B=64, C=128, H=36, W=100), weights (C, C, KS=9), fp32.
// Fully in-place in d_out after a single x->out copy.

#define B_ 64
#define C_ 128
#define H_ 36
#define W_ 100
#define KS_ 9
#define CH_STRIDE (H_ * W_)          // 3600
#define B_STRIDE  (C_ * H_ * W_)     // 460800

// Transposed weights: [dir][(ci*KS + k)*C + co]  -> coalesced per-thread (co) loads
__device__ float g_wT[4][C_ * KS_ * C_];

__global__ void transpose_weights_kernel(const float* __restrict__ wd,
                                         const float* __restrict__ wu,
                                         const float* __restrict__ wr,
                                         const float* __restrict__ wl) {
    int idx = blockIdx.x * blockDim.x + threadIdx.x;
    const int total = C_ * C_ * KS_;
    if (idx >= total) return;
    int co  = idx / (C_ * KS_);
    int rem = idx % (C_ * KS_);      // ci*KS + k
    g_wT[0][rem * C_ + co] = wd[idx];
    g_wT[1][rem * C_ + co] = wu[idx];
    g_wT[2][rem * C_ + co] = wr[idx];
    g_wT[3][rem * C_ + co] = wl[idx];
}

// One scan step.
//   SUB      : line positions computed per thread
//   L        : length of the conv line (W for H-scans, H for W-scans)
//   ESTRIDE  : element stride along the conv line (1 for H-scans, W for W-scans)
// Block: 256 threads = co (128) x sub-tile (2). Grid: (2 line-tiles, B batches).
// prevOff / curOff: element offsets (within a batch) selecting the prev / current
// scan-position slab.
template <int SUB, int L, int ESTRIDE>
__global__ void __launch_bounds__(256) step_kernel(float* __restrict__ out,
                                                   int dir, int prevOff, int curOff) {
    constexpr int LT  = 2 * SUB;          // lines per block
    constexpr int WIN = LT + KS_ - 1;     // smem window per channel
    __shared__ float s_prev[C_ * WIN];

    const int b     = blockIdx.y;
    const int tile0 = blockIdx.x * LT;
    const int tid   = threadIdx.x;

    const float* __restrict__ prevBase = out + (size_t)b * B_STRIDE + prevOff;

    // Stage prev line (all 128 channels, window incl. halo) into smem.
    for (int i = tid; i < C_ * WIN; i += 256) {
        int ci   = i / WIN;
        int j    = i % WIN;
        int line = tile0 - (KS_ / 2) + j;
        float v = 0.0f;
        if (line >= 0 && line < L)
            v = prevBase[ci * CH_STRIDE + line * ESTRIDE];
        s_prev[ci * WIN + j] = v;
    }
    __syncthreads();

    const int co   = tid & (C_ - 1);
    const int sub  = tid >> 7;            // 0 or 1
    const int base = sub * SUB;

    float acc[SUB];
#pragma unroll
    for (int j = 0; j < SUB; j++) acc[j] = 0.0f;

    const float* __restrict__ wT = g_wT[dir] + co;

#pragma unroll 1
    for (int ci = 0; ci < C_; ci++) {
        float win[SUB + KS_ - 1];
#pragma unroll
        for (int j = 0; j < SUB + KS_ - 1; j++)
            win[j] = s_prev[ci * WIN + base + j];
        const float* __restrict__ wp = wT + ci * (KS_ * C_);
#pragma unroll
        for (int k = 0; k < KS_; k++) {
            float wv = __ldg(wp + k * C_);
#pragma unroll
            for (int j = 0; j < SUB; j++)
                acc[j] = fmaf(wv, win[j + k], acc[j]);
        }
    }

    float* __restrict__ curBase = out + (size_t)b * B_STRIDE + co * CH_STRIDE + curOff;
    const int line0 = tile0 + base;
#pragma unroll
    for (int j = 0; j < SUB; j++) {
        float* p = curBase + (line0 + j) * ESTRIDE;
        *p = *p + fmaxf(acc[j], 0.0f);
    }
}

extern "C" void kernel_launch(void* const* d_in, const int* in_sizes, int n_in,
                              void* d_out, int out_size) {
    const float* x = (const float*)d_in[0];
    float* out = (float*)d_out;
    (void)in_sizes; (void)n_in; (void)out_size;

    // out = x  (scan 1 accumulates into it; all scans run in-place)
    cudaMemcpyAsync(out, x, (size_t)B_ * C_ * H_ * W_ * sizeof(float),
                    cudaMemcpyDeviceToDevice, 0);

    transpose_weights_kernel<<<(C_ * C_ * KS_ + 255) / 256, 256>>>(
        (const float*)d_in[1], (const float*)d_in[2],
        (const float*)d_in[3], (const float*)d_in[4]);

    const dim3 gridH(2, B_);   // 2 tiles of 50 over W=100
    const dim3 gridW(2, B_);   // 2 tiles of 18 over H=36

    // Scan 1: down (axis H, forward), conv along W, weights w_d (dir 0)
    for (int h = 1; h < H_; h++)
        step_kernel<25, W_, 1><<<gridH, 256>>>(out, 0, (h - 1) * W_, h * W_);

    // Scan 2: up (axis H, reverse), weights w_u (dir 1)
    for (int h = H_ - 2; h >= 0; h--)
        step_kernel<25, W_, 1><<<gridH, 256>>>(out, 1, (h + 1) * W_, h * W_);

    // Scan 3: right (axis W, forward), conv along H, weights w_r (dir 2)
    for (int w = 1; w < W_; w++)
        step_kernel<9, H_, W_><<<gridW, 256>>>(out, 2, w - 1, w);

    // Scan 4: left (axis W, reverse), weights w_l (dir 3)
    for (int w = W_ - 2; w >= 0; w--)
        step_kernel<9, H_, W_><<<gridW, 256>>>(out, 3, w + 1, w);
}

// round 2
// speedup vs baseline: 1.0020x; 1.0020x over previous
#include <cuda_runtime.h>

// SpatialCNN: 4 directional scans, each step: out[p] += relu(conv1d_C2C(out[p_prev]))
// Shapes: x (B=64, C=128, H=36, W=100), weights (C, C, KS=9), fp32.
// Fully in-place in d_out after a single x->out copy.

#define B_ 64
#define C_ 128
#define H_ 36
#define W_ 100
#define KS_ 9
#define CH_STRIDE (H_ * W_)          // 3600
#define B_STRIDE  (C_ * H_ * W_)     // 460800

// Transposed weights: [dir][(ci*KS + k)*C + co]  -> coalesced per-thread (co) loads
__device__ float g_wT[4][C_ * KS_ * C_];

__global__ void transpose_weights_kernel(const float* __restrict__ wd,
                                         const float* __restrict__ wu,
                                         const float* __restrict__ wr,
                                         const float* __restrict__ wl) {
    int idx = blockIdx.x * blockDim.x + threadIdx.x;
    const int total = C_ * C_ * KS_;
    if (idx >= total) return;
    int co  = idx / (C_ * KS_);
    int rem = idx % (C_ * KS_);      // ci*KS + k
    g_wT[0][rem * C_ + co] = wd[idx];
    g_wT[1][rem * C_ + co] = wu[idx];
    g_wT[2][rem * C_ + co] = wr[idx];
    g_wT[3][rem * C_ + co] = wl[idx];
}

// One scan step.
//   SUBS     : sub-tiles per block (block = 128*SUBS threads)
//   SUB      : line positions computed per thread (kept small so acc+win+wv fit regs)
//   L        : length of the conv line (W for H-scans, H for W-scans)
//   ESTRIDE  : element stride along the conv line (1 for H-scans, W for W-scans)
// Grid: (tiles, B). prevOff/curOff: element offsets within a batch.
template <int SUBS, int SUB, int L, int ESTRIDE>
__global__ void __launch_bounds__(128 * SUBS)
step_kernel(float* __restrict__ out, int dir, int prevOff, int curOff) {
    constexpr int LT  = SUBS * SUB;       // lines per block
    constexpr int WIN = LT + KS_ - 1;     // smem window per channel
    __shared__ float s_prev[C_ * WIN];

    const int b     = blockIdx.y;
    const int tile0 = blockIdx.x * LT;
    const int tid   = threadIdx.x;

    const float* __restrict__ prevBase = out + (size_t)b * B_STRIDE + prevOff;

    // Stage prev line (all 128 channels, window incl. halo) into smem.
    for (int i = tid; i < C_ * WIN; i += 128 * SUBS) {
        int ci   = i / WIN;
        int j    = i % WIN;
        int line = tile0 - (KS_ / 2) + j;
        float v = 0.0f;
        if (line >= 0 && line < L)
            v = prevBase[ci * CH_STRIDE + line * ESTRIDE];
        s_prev[i] = v;
    }
    __syncthreads();

    const int co   = tid & (C_ - 1);
    const int sub  = tid >> 7;            // 0..SUBS-1
    const int base = sub * SUB;

    float acc[SUB];
#pragma unroll
    for (int j = 0; j < SUB; j++) acc[j] = 0.0f;

    const float* __restrict__ wT = g_wT[dir] + co;

#pragma unroll 1
    for (int ci = 0; ci < C_; ci++) {
        // Preload all 9 weights for this ci first (independent LDGs -> MLP)
        float wv[KS_];
#pragma unroll
        for (int k = 0; k < KS_; k++)
            wv[k] = __ldg(wT + (ci * KS_ + k) * C_);

        float win[SUB + KS_ - 1];
#pragma unroll
        for (int j = 0; j < SUB + KS_ - 1; j++)
            win[j] = s_prev[ci * WIN + base + j];

#pragma unroll
        for (int k = 0; k < KS_; k++) {
#pragma unroll
            for (int j = 0; j < SUB; j++)
                acc[j] = fmaf(wv[k], win[j + k], acc[j]);
        }
    }

    float* __restrict__ curBase = out + (size_t)b * B_STRIDE + co * CH_STRIDE + curOff;
    const int line0 = tile0 + base;
#pragma unroll
    for (int j = 0; j < SUB; j++) {
        int line = line0 + j;
        if (line < L) {
            float* p = curBase + line * ESTRIDE;
            *p = *p + fmaxf(acc[j], 0.0f);
        }
    }
}

extern "C" void kernel_launch(void* const* d_in, const int* in_sizes, int n_in,
                              void* d_out, int out_size) {
    const float* x = (const float*)d_in[0];
    float* out = (float*)d_out;
    (void)in_sizes; (void)n_in; (void)out_size;

    // out = x  (scan 1 accumulates into it; all scans run in-place)
    cudaMemcpyAsync(out, x, (size_t)B_ * C_ * H_ * W_ * sizeof(float),
                    cudaMemcpyDeviceToDevice, 0);

    transpose_weights_kernel<<<(C_ * C_ * KS_ + 255) / 256, 256>>>(
        (const float*)d_in[1], (const float*)d_in[2],
        (const float*)d_in[3], (const float*)d_in[4]);

    // H-scans: conv along W (L=100, stride 1). Block 640 = 128co x 5sub, SUB=10,
    // LT=50 -> 2 tiles. Grid 128 blocks, 20 warps/SM.
    const dim3 gridH(2, B_);
    // W-scans: conv along H (L=36, stride W). Block 640, SUB=4, LT=20 -> 2 tiles (covers 40, guarded).
    const dim3 gridW(2, B_);

    // Scan 1: down (axis H, forward), weights w_d (dir 0)
    for (int h = 1; h < H_; h++)
        step_kernel<5, 10, W_, 1><<<gridH, 640>>>(out, 0, (h - 1) * W_, h * W_);

    // Scan 2: up (axis H, reverse), weights w_u (dir 1)
    for (int h = H_ - 2; h >= 0; h--)
        step_kernel<5, 10, W_, 1><<<gridH, 640>>>(out, 1, (h + 1) * W_, h * W_);

    // Scan 3: right (axis W, forward), weights w_r (dir 2)
    for (int w = 1; w < W_; w++)
        step_kernel<5, 4, H_, W_><<<gridW, 640>>>(out, 2, w - 1, w);

    // Scan 4: left (axis W, reverse), weights w_l (dir 3)
    for (int w = W_ - 2; w >= 0; w--)
        step_kernel<5, 4, H_, W_><<<gridW, 640>>>(out, 3, w + 1, w);
}

// round 3
// speedup vs baseline: 1.6965x; 1.6931x over previous
#include <cuda_runtime.h>

// SpatialCNN: 4 directional scans, each step: out[p] += relu(conv1d_C2C(out[p_prev]))
// x (B=64, C=128, H=36, W=100), weights (C, C, KS=9), fp32. In-place in d_out.
// Each step is a GEMM: M=128(co), K=1152(ci*9), N=B*L. Register-blocked GEMM with
// weights double-buffered through SMEM and im2col read from the staged prev window.

#define B_ 64
#define C_ 128
#define H_ 36
#define W_ 100
#define KS_ 9
#define CH_STRIDE (H_ * W_)          // 3600
#define B_STRIDE  (C_ * H_ * W_)     // 460800
#define KTOT (C_ * KS_)              // 1152

// Transposed weights: [dir][(ci*KS + k)*C + co]
__device__ float g_wT[4][KTOT * C_];

__global__ void transpose_weights_kernel(const float* __restrict__ wd,
                                         const float* __restrict__ wu,
                                         const float* __restrict__ wr,
                                         const float* __restrict__ wl) {
    int idx = blockIdx.x * blockDim.x + threadIdx.x;
    const int total = C_ * C_ * KS_;
    if (idx >= total) return;
    int co  = idx / (C_ * KS_);
    int rem = idx % (C_ * KS_);      // ci*KS + k
    g_wT[0][rem * C_ + co] = wd[idx];
    g_wT[1][rem * C_ + co] = wu[idx];
    g_wT[2][rem * C_ + co] = wr[idx];
    g_wT[3][rem * C_ + co] = wl[idx];
}

// GEMM-shaped scan step.
//   MT x NT : block tile (co x line positions). MM x NN : per-thread micro-tile.
//   L       : conv line length, ES: element stride along line.
//   NTILES  : # of n-tiles (blockIdx.x = mtile*NTILES + ntile).
// THREADS = (MT/MM)*(NT/NN) chosen so all warps are full and SMSP-balanced.
template <int MT, int NT, int MM, int NN, int L, int ES, int NTILES>
__global__ void __launch_bounds__((MT / MM) * (NT / NN), 1)
gemm_step(float* __restrict__ out, int dir, int prevOff, int curOff) {
    constexpr int THREADS = (MT / MM) * (NT / NN);
    constexpr int NTHR_N  = NT / NN;
    constexpr int WIN     = NT + KS_ - 1;
    constexpr int CI_CH   = 16;
    constexpr int KKC     = CI_CH * KS_;        // 144 kk per chunk
    constexpr int NCH     = C_ / CI_CH;         // 8 chunks
    constexpr int CHUNK4  = KKC * MT / 4;       // float4s per A chunk
    constexpr int NLD     = (CHUNK4 + THREADS - 1) / THREADS;

    extern __shared__ float smem[];
    float* sA = smem;                    // 2 * KKC * MT  (double-buffered weights)
    float* sP = smem + 2 * KKC * MT;     // C_ * WIN      (prev window, im2col source)

    const int b     = blockIdx.y;
    const int ntile = blockIdx.x % NTILES;
    const int mo    = (blockIdx.x / NTILES) * MT;
    const int tid   = threadIdx.x;
    const int tn    = tid % NTHR_N;
    const int tm    = tid / NTHR_N;
    const int n0    = tn * NN;
    const int co0   = tm * MM;

    const float* __restrict__ wT = g_wT[dir];

    // Stage prev window (all 128 channels + halo) into smem.
    {
        const float* __restrict__ prevBase = out + (size_t)b * B_STRIDE + prevOff;
        const int lineBase = ntile * NT - KS_ / 2;
        for (int i = tid; i < C_ * WIN; i += THREADS) {
            int ci = i / WIN, j = i % WIN;
            int line = lineBase + j;
            float v = 0.0f;
            if (line >= 0 && line < L)
                v = prevBase[ci * CH_STRIDE + line * ES];
            sP[i] = v;
        }
    }
    // Stage A chunk 0.
    {
        const float* __restrict__ gA = wT + mo;
        for (int idx = tid; idx < CHUNK4; idx += THREADS) {
            int r = idx / (MT / 4), cc = idx % (MT / 4);
            ((float4*)sA)[idx] = ((const float4*)(gA + r * C_))[cc];
        }
    }
    __syncthreads();

    float acc[MM][NN];
#pragma unroll
    for (int m = 0; m < MM; m++)
#pragma unroll
        for (int n = 0; n < NN; n++) acc[m][n] = 0.0f;

    for (int c = 0; c < NCH; c++) {
        // Issue next chunk's LDGs before compute (latency hidden by FMAs).
        float4 buf[NLD];
        if (c + 1 < NCH) {
            const float* __restrict__ gA = wT + (c + 1) * KKC * C_ + mo;
#pragma unroll
            for (int j = 0; j < NLD; j++) {
                int idx = tid + j * THREADS;
                if (idx < CHUNK4) {
                    int r = idx / (MT / 4), cc = idx % (MT / 4);
                    buf[j] = ((const float4*)(gA + r * C_))[cc];
                }
            }
        }

        const float* __restrict__ sAc = sA + (c & 1) * (KKC * MT);
#pragma unroll 1
        for (int cl = 0; cl < CI_CH; cl++) {
            const int ci = c * CI_CH + cl;
            float win[NN + KS_ - 1];
#pragma unroll
            for (int j = 0; j < NN + KS_ - 1; j++)
                win[j] = sP[ci * WIN + n0 + j];
            const float* __restrict__ ap = sAc + cl * (KS_ * MT) + co0;
#pragma unroll
            for (int k = 0; k < KS_; k++) {
                float a[MM];
#pragma unroll
                for (int m = 0; m < MM; m++) a[m] = ap[k * MT + m];
#pragma unroll
                for (int m = 0; m < MM; m++)
#pragma unroll
                    for (int n = 0; n < NN; n++)
                        acc[m][n] = fmaf(a[m], win[n + k], acc[m][n]);
            }
        }

        if (c + 1 < NCH) {
            float* __restrict__ sAn = sA + ((c + 1) & 1) * (KKC * MT);
#pragma unroll
            for (int j = 0; j < NLD; j++) {
                int idx = tid + j * THREADS;
                if (idx < CHUNK4) ((float4*)sAn)[idx] = buf[j];
            }
        }
        __syncthreads();
    }

    // Epilogue: out[cur] += relu(acc). NT divides the line exactly -> no guards.
    float* __restrict__ curBase = out + (size_t)b * B_STRIDE + curOff;
#pragma unroll
    for (int m = 0; m < MM; m++) {
        const int co = mo + co0 + m;
#pragma unroll
        for (int n = 0; n < NN; n++) {
            const int line = ntile * NT + n0 + n;
            float* p = curBase + co * CH_STRIDE + line * ES;
            *p = *p + fmaxf(acc[m][n], 0.0f);
        }
    }
}

// H-steps: conv along W. tile 128co x 50n, micro 2x5, 640 thr (20 warps, balanced).
#define SMEM_H ((2 * 144 * 128 + 128 * (50 + 8)) * 4)
// W-steps: conv along H. tile 64co x 36n, micro 2x3, 384 thr (12 warps, balanced).
#define SMEM_W ((2 * 144 * 64 + 128 * (36 + 8)) * 4)

extern "C" void kernel_launch(void* const* d_in, const int* in_sizes, int n_in,
                              void* d_out, int out_size) {
    const float* x = (const float*)d_in[0];
    float* out = (float*)d_out;
    (void)in_sizes; (void)n_in; (void)out_size;

    static bool attr_done = false;
    if (!attr_done) {
        cudaFuncSetAttribute((const void*)gemm_step<128, 50, 2, 5, W_, 1, 2>,
                             cudaFuncAttributeMaxDynamicSharedMemorySize, SMEM_H);
        cudaFuncSetAttribute((const void*)gemm_step<64, 36, 2, 3, H_, W_, 1>,
                             cudaFuncAttributeMaxDynamicSharedMemorySize, SMEM_W);
        attr_done = true;
    }

    // out = x (all scans run in-place, accumulating)
    cudaMemcpyAsync(out, x, (size_t)B_ * C_ * H_ * W_ * sizeof(float),
                    cudaMemcpyDeviceToDevice, 0);

    transpose_weights_kernel<<<(C_ * C_ * KS_ + 255) / 256, 256>>>(
        (const float*)d_in[1], (const float*)d_in[2],
        (const float*)d_in[3], (const float*)d_in[4]);

    const dim3 gridH(2, B_);   // 2 n-tiles of 50 over W=100, 1 m-tile
    const dim3 gridW(2, B_);   // 2 m-tiles of 64 co, 1 n-tile of 36

    // Scan 1: down (axis H, forward), w_d
    for (int h = 1; h < H_; h++)
        gemm_step<128, 50, 2, 5, W_, 1, 2><<<gridH, 640, SMEM_H>>>(out, 0, (h - 1) * W_, h * W_);

    // Scan 2: up (axis H, reverse), w_u
    for (int h = H_ - 2; h >= 0; h--)
        gemm_step<128, 50, 2, 5, W_, 1, 2><<<gridH, 640, SMEM_H>>>(out, 1, (h + 1) * W_, h * W_);

    // Scan 3: right (axis W, forward), w_r
    for (int w = 1; w < W_; w++)
        gemm_step<64, 36, 2, 3, H_, W_, 1><<<gridW, 384, SMEM_W>>>(out, 2, w - 1, w);

    // Scan 4: left (axis W, reverse), w_l
    for (int w = W_ - 2; w >= 0; w--)
        gemm_step<64, 36, 2, 3, H_, W_, 1><<<gridW, 384, SMEM_W>>>(out, 3, w + 1, w);
}